// round 6
// baseline (speedup 1.0000x reference)
#include <cuda_runtime.h>
#include <cuda_fp16.h>
#include <cstdint>

// ================= problem constants =================
#define Mdim 4096
#define Ndim 8192          // 4 gates x 2048, interleaved: n = col*4 + gate
#define Kdim 4096          // [x | h]
#define BM 256
#define BN 128
#define BK 32
#define NKT (Kdim / BK)    // 128
#define THREADS 256        // 8 warps, 4m x 2n, warp tile 64x64

// smem layout (halves): pitch 40 halves (80B) -> ldmatrix conflict-free
#define APITCH 40
#define BPITCH 40
#define AHALVES (BM * APITCH)            // 10240
#define BHALVES (BN * BPITCH)            // 5120
#define STAGE_H (AHALVES + BHALVES)      // 15360 halves = 30720 B
#define NSTAGE 4
// epilogue float buffers (reuse stage area): 3 x 256 x 33 floats
#define EPITCH 33
#define EBUF_W (BM * EPITCH)             // 8448 words
#define SMEM_BYTES (512 + NSTAGE * STAGE_H * 2)   // 123392 (> 3*EBUF_W*4)

// ================= scratch =================
__device__ __half g_A[(size_t)Mdim * Kdim];   // 32 MB, [m][k]
__device__ __half g_B[(size_t)Ndim * Kdim];   // 64 MB, [n][k] (transposed)

// ================= helpers =================
__device__ __forceinline__ void cp16(uint32_t dst, const void* src) {
    asm volatile("cp.async.cg.shared.global [%0], [%1], 16;" :: "r"(dst), "l"(src) : "memory");
}
#define CP_COMMIT() asm volatile("cp.async.commit_group;" ::: "memory")
#define CP_WAIT(n)  asm volatile("cp.async.wait_group %0;" :: "n"(n) : "memory")

#define LDSM4(r0, r1, r2, r3, addr) \
    asm volatile("ldmatrix.sync.aligned.m8n8.x4.shared.b16 {%0,%1,%2,%3}, [%4];" \
        : "=r"(r0), "=r"(r1), "=r"(r2), "=r"(r3) : "r"(addr))

#define MMA16(acc, A, B) \
    asm volatile("mma.sync.aligned.m16n8k16.row.col.f32.f16.f16.f32 " \
        "{%0,%1,%2,%3}, {%4,%5,%6,%7}, {%8,%9}, {%0,%1,%2,%3};" \
        : "+f"((acc)[0]), "+f"((acc)[1]), "+f"((acc)[2]), "+f"((acc)[3]) \
        : "r"((A)[0]), "r"((A)[1]), "r"((A)[2]), "r"((A)[3]), \
          "r"((B)[0]), "r"((B)[1]))

__device__ __forceinline__ float sigm(float x) {
    return __fdividef(1.0f, 1.0f + __expf(-x));
}
__device__ __forceinline__ float tanh_f(float x) {
    float xc = fmaxf(fminf(x, 15.0f), -15.0f);
    float e = __expf(2.0f * xc);
    return __fdividef(e - 1.0f, e + 1.0f);
}

// ========== merged pre-pass: A convert + B transpose (one launch) ==========
// blocks [0, 16384): A path.  blocks [16384, 49152): B path (128k x 64c x 4g)
__global__ void __launch_bounds__(256) conv_kernel(
    const float* __restrict__ x,   const float* __restrict__ h,
    const float* __restrict__ wxi, const float* __restrict__ wxf,
    const float* __restrict__ wxo, const float* __restrict__ wxc,
    const float* __restrict__ whi, const float* __restrict__ whf,
    const float* __restrict__ who, const float* __restrict__ whc) {
    int tid = threadIdx.x;
    if (blockIdx.x < 16384) {
        size_t i = (size_t)blockIdx.x * 256 + tid;       // float4 units: 4096*1024
        size_t row = i >> 10;
        size_t c4  = i & 1023;
        const float* src = (c4 < 512) ? (x + row * 2048 + c4 * 4)
                                      : (h + row * 2048 + (c4 - 512) * 4);
        float4 v = *(const float4*)src;
        *(__half2*)(g_A + row * 4096 + c4 * 4)     = __floats2half2_rn(v.x, v.y);
        *(__half2*)(g_A + row * 4096 + c4 * 4 + 2) = __floats2half2_rn(v.z, v.w);
    } else {
        __shared__ float tile[32][33];
        int bid = blockIdx.x - 16384;
        int kt = bid & 127;
        int ct = (bid >> 7) & 63;
        int g  = bid >> 13;
        int tx = tid & 31, ty = tid >> 5;
        int k0 = kt * 32, c0 = ct * 32;
        const float* src;
        int krel = (k0 < 2048) ? k0 : k0 - 2048;
        if (k0 < 2048)
            src = (g == 0) ? wxi : (g == 1) ? wxf : (g == 2) ? wxo : wxc;
        else
            src = (g == 0) ? whi : (g == 1) ? whf : (g == 2) ? who : whc;
        #pragma unroll
        for (int r = ty; r < 32; r += 8)
            tile[r][tx] = src[(size_t)(krel + r) * 2048 + c0 + tx];
        __syncthreads();
        #pragma unroll
        for (int r = ty; r < 32; r += 8) {
            size_t n = (size_t)(c0 + r) * 4 + g;
            g_B[n * 4096 + k0 + tx] = __float2half_rn(tile[tx][r]);
        }
    }
}

// ================= main fused GEMM + LSTM =================
__global__ void __launch_bounds__(THREADS, 1) lstm_gemm_kernel(
    const float* __restrict__ c_in,
    const float* __restrict__ b_i, const float* __restrict__ b_f,
    const float* __restrict__ b_o, const float* __restrict__ b_c,
    float* __restrict__ out) {
    extern __shared__ float sm[];
    float* bias_sm = sm;                       // 128 floats [hc*4+gate]
    __half* stage  = (__half*)(sm + 128);

    const int tid  = threadIdx.x;
    const int lane = tid & 31;
    const int wid  = tid >> 5;
    const int wm   = wid >> 1;                 // 0..3 -> m offset wm*64
    const int wn   = wid & 1;                  // 0..1 -> n offset wn*64
    const int m0   = blockIdx.x * BM;
    const int n0   = blockIdx.y * BN;
    const int hc0  = blockIdx.y * 32;

    if (tid < 128) {
        int g = tid & 3, hc = tid >> 2;
        const float* bp = (g == 0) ? b_i : (g == 1) ? b_f : (g == 2) ? b_o : b_c;
        bias_sm[tid] = bp[hc0 + hc];
    }

    const uint32_t stage_u32 = (uint32_t)__cvta_generic_to_shared(stage);

    // -------- cp.async stage issue: A 1024 + B 512 chunks (16B each) --------
    auto issue = [&](int s, int kt) {
        uint32_t As = stage_u32 + (uint32_t)(s * STAGE_H) * 2;
        uint32_t Bs = As + AHALVES * 2;
        int k0 = kt * BK;
        #pragma unroll
        for (int it = 0; it < 4; it++) {               // A
            int ch  = tid + it * THREADS;
            int row = ch >> 2, kc = ch & 3;
            cp16(As + (uint32_t)(row * APITCH + kc * 8) * 2,
                 g_A + (size_t)(m0 + row) * 4096 + k0 + kc * 8);
        }
        #pragma unroll
        for (int it = 0; it < 2; it++) {               // B
            int ch  = tid + it * THREADS;
            int row = ch >> 2, kc = ch & 3;
            cp16(Bs + (uint32_t)(row * BPITCH + kc * 8) * 2,
                 g_B + (size_t)(n0 + row) * 4096 + k0 + kc * 8);
        }
    };

    issue(0, 0); CP_COMMIT();
    issue(1, 1); CP_COMMIT();
    issue(2, 2); CP_COMMIT();

    float acc[4][8][4];                          // 128 regs: 4 m-sub x 8 n8-sub
    #pragma unroll
    for (int a = 0; a < 4; a++)
        #pragma unroll
        for (int b = 0; b < 8; b++)
            #pragma unroll
            for (int q = 0; q < 4; q++) acc[a][b][q] = 0.0f;

    // ldmatrix lane offsets
    const uint32_t a_lane_off =
        ((uint32_t)((wm * 64 + (lane & 15)) * APITCH + (lane >> 4) * 8)) * 2;
    const uint32_t b_lane_off =
        ((uint32_t)((wn * 64 + (lane & 7) + ((lane >> 4) << 3)) * BPITCH
                    + ((lane >> 3) & 1) * 8)) * 2;

    int s = 0;
    for (int kt = 0; kt < NKT; kt++) {
        CP_WAIT(2);
        __syncthreads();
        uint32_t As = stage_u32 + (uint32_t)(s * STAGE_H) * 2;
        uint32_t Bs = As + AHALVES * 2;
        #pragma unroll
        for (int k16 = 0; k16 < 2; k16++) {
            uint32_t koff = (uint32_t)(k16 * 16) * 2;
            uint32_t bf[8][2];
            #pragma unroll
            for (int np = 0; np < 4; np++) {           // n-pair: ns=2np, 2np+1
                uint32_t r0, r1, r2, r3;
                LDSM4(r0, r1, r2, r3,
                      Bs + b_lane_off + (uint32_t)(np * 16 * BPITCH) * 2 + koff);
                bf[2 * np][0] = r0;     bf[2 * np][1] = r1;
                bf[2 * np + 1][0] = r2; bf[2 * np + 1][1] = r3;
            }
            #pragma unroll
            for (int ms = 0; ms < 4; ms++) {
                uint32_t af[4];
                LDSM4(af[0], af[1], af[2], af[3],
                      As + a_lane_off + (uint32_t)(ms * 16 * APITCH) * 2 + koff);
                #pragma unroll
                for (int ns = 0; ns < 8; ns++) MMA16(acc[ms][ns], af, bf[ns]);
            }
        }
        if (kt + 3 < NKT) issue((kt + 3) & 3, kt + 3);
        CP_COMMIT();
        s = (s + 1) & 3;
    }

    CP_WAIT(0);
    __syncthreads();

    // -------- epilogue --------
    float* ebase = sm + 128;
    float* cbuf  = ebase;
    float* hbuf  = ebase + EBUF_W;
    float* cobuf = ebase + 2 * EBUF_W;

    #pragma unroll
    for (int it = 0; it < 8; it++) {
        int idx = tid + it * THREADS;                  // 2048 float4 loads
        int row = idx >> 3, q = idx & 7;
        float4 v = *(const float4*)(c_in + (size_t)(m0 + row) * 2048 + hc0 + q * 4);
        float* d = cbuf + row * EPITCH + q * 4;
        d[0] = v.x; d[1] = v.y; d[2] = v.z; d[3] = v.w;
    }
    __syncthreads();

    const bool odd = lane & 1;
    #pragma unroll
    for (int ms = 0; ms < 4; ms++) {
        #pragma unroll
        for (int ns = 0; ns < 8; ns++) {
            float t0 = __shfl_xor_sync(0xFFFFFFFFu, acc[ms][ns][0], 1);
            float t1 = __shfl_xor_sync(0xFFFFFFFFu, acc[ms][ns][1], 1);
            float t2 = __shfl_xor_sync(0xFFFFFFFFu, acc[ms][ns][2], 1);
            float t3 = __shfl_xor_sync(0xFFFFFFFFu, acc[ms][ns][3], 1);
            float gi = odd ? t2 : acc[ms][ns][0];
            float gf = odd ? t3 : acc[ms][ns][1];
            float go = odd ? acc[ms][ns][2] : t0;
            float gg = odd ? acc[ms][ns][3] : t1;
            int rowl = wm * 64 + ms * 16 + (lane >> 2) + (odd ? 8 : 0);
            int hc   = wn * 16 + ns * 2 + ((lane >> 1) & 1);
            gi += bias_sm[hc * 4 + 0];
            gf += bias_sm[hc * 4 + 1];
            go += bias_sm[hc * 4 + 2];
            gg += bias_sm[hc * 4 + 3];
            float it_ = sigm(gi);
            float ft_ = sigm(gf);
            float ot_ = sigm(go);
            float ct  = cbuf[rowl * EPITCH + hc] * ft_ + it_ * tanh_f(gg);
            float ht  = ot_ * tanh_f(ct);
            hbuf[rowl * EPITCH + hc]  = ht;
            cobuf[rowl * EPITCH + hc] = ct;
        }
    }
    __syncthreads();

    float* out_c = out + (size_t)4096 * 2048;
    #pragma unroll
    for (int it = 0; it < 8; it++) {
        int idx = tid + it * THREADS;
        int row = idx >> 3, q = idx & 7;
        size_t g = (size_t)(m0 + row) * 2048 + hc0 + q * 4;
        const float* hsrc = hbuf + row * EPITCH + q * 4;
        const float* csrc = cobuf + row * EPITCH + q * 4;
        float4 hv = {hsrc[0], hsrc[1], hsrc[2], hsrc[3]};
        float4 cv = {csrc[0], csrc[1], csrc[2], csrc[3]};
        *(float4*)(out + g)   = hv;
        *(float4*)(out_c + g) = cv;
    }
}

// ================= host =================
extern "C" void kernel_launch(void* const* d_in, const int* in_sizes, int n_in,
                              void* d_out, int out_size) {
    (void)in_sizes; (void)n_in; (void)out_size;
    const float* x    = (const float*)d_in[0];
    const float* h    = (const float*)d_in[1];
    const float* c    = (const float*)d_in[2];
    const float* w_xi = (const float*)d_in[3];
    const float* w_hi = (const float*)d_in[4];
    const float* w_xf = (const float*)d_in[5];
    const float* w_hf = (const float*)d_in[6];
    const float* w_xo = (const float*)d_in[7];
    const float* w_ho = (const float*)d_in[8];
    const float* w_xc = (const float*)d_in[9];
    const float* w_hc = (const float*)d_in[10];
    const float* b_i  = (const float*)d_in[11];
    const float* b_f  = (const float*)d_in[12];
    const float* b_o  = (const float*)d_in[13];
    const float* b_c  = (const float*)d_in[14];

    conv_kernel<<<49152, 256>>>(x, h, w_xi, w_xf, w_xo, w_xc,
                                w_hi, w_hf, w_ho, w_hc);

    cudaFuncSetAttribute(lstm_gemm_kernel,
                         cudaFuncAttributeMaxDynamicSharedMemorySize, SMEM_BYTES);
    dim3 grid(Mdim / BM, Ndim / BN, 1);   // (16, 64)
    lstm_gemm_kernel<<<grid, THREADS, SMEM_BYTES>>>(c, b_i, b_f, b_o, b_c, (float*)d_out);
}

// round 7
// speedup vs baseline: 1.2050x; 1.2050x over previous
#include <cuda_runtime.h>
#include <cuda_fp16.h>
#include <cstdint>

// ================= problem constants =================
#define Mdim 4096
#define Ndim 8192          // 4 gates x 2048, interleaved: n = col*4 + gate
#define Kdim 4096          // [x | h]
#define BM 256
#define BN 128
#define BK 64
#define NKT (Kdim / BK)    // 64
#define THREADS 256        // 8 warps, 4m x 2n, warp tile 64x64

// smem (halves): pitch 72 halves (144B) -> ldmatrix conflict-free (16B phase shift/row)
#define APITCH 72
#define BPITCH 72
#define AHALVES (BM * APITCH)            // 18432
#define BHALVES (BN * BPITCH)            // 9216
#define STAGE_H (AHALVES + BHALVES)      // 27648 halves = 55296 B
#define NSTAGE 3
#define SMEM_BYTES (512 + NSTAGE * STAGE_H * 2)   // 166400
// epilogue float buffers reuse stage area: 3 x 256 x 33 floats = 101376 B (fits)
#define EPITCH 33
#define EBUF_W (BM * EPITCH)

// ================= scratch =================
__device__ __half g_A[(size_t)Mdim * Kdim];   // 32 MB, [m][k]
__device__ __half g_B[(size_t)Ndim * Kdim];   // 64 MB, [n][k] (transposed)

// ================= helpers =================
__device__ __forceinline__ void cp16(uint32_t dst, const void* src) {
    asm volatile("cp.async.cg.shared.global [%0], [%1], 16;" :: "r"(dst), "l"(src) : "memory");
}
#define CP_COMMIT() asm volatile("cp.async.commit_group;" ::: "memory")
#define CP_WAIT(n)  asm volatile("cp.async.wait_group %0;" :: "n"(n) : "memory")

#define LDSM4(r0, r1, r2, r3, addr) \
    asm volatile("ldmatrix.sync.aligned.m8n8.x4.shared.b16 {%0,%1,%2,%3}, [%4];" \
        : "=r"(r0), "=r"(r1), "=r"(r2), "=r"(r3) : "r"(addr))

#define MMA16(acc, A, B) \
    asm volatile("mma.sync.aligned.m16n8k16.row.col.f32.f16.f16.f32 " \
        "{%0,%1,%2,%3}, {%4,%5,%6,%7}, {%8,%9}, {%0,%1,%2,%3};" \
        : "+f"((acc)[0]), "+f"((acc)[1]), "+f"((acc)[2]), "+f"((acc)[3]) \
        : "r"((A)[0]), "r"((A)[1]), "r"((A)[2]), "r"((A)[3]), \
          "r"((B)[0]), "r"((B)[1]))

__device__ __forceinline__ float sigm(float x) {
    return __fdividef(1.0f, 1.0f + __expf(-x));
}
__device__ __forceinline__ float tanh_f(float x) {
    float xc = fmaxf(fminf(x, 15.0f), -15.0f);
    float e = __expf(2.0f * xc);
    return __fdividef(e - 1.0f, e + 1.0f);
}

// ========== merged pre-pass: A convert + B transpose (one launch) ==========
__global__ void __launch_bounds__(256) conv_kernel(
    const float* __restrict__ x,   const float* __restrict__ h,
    const float* __restrict__ wxi, const float* __restrict__ wxf,
    const float* __restrict__ wxo, const float* __restrict__ wxc,
    const float* __restrict__ whi, const float* __restrict__ whf,
    const float* __restrict__ who, const float* __restrict__ whc) {
    int tid = threadIdx.x;
    if (blockIdx.x < 16384) {
        size_t i = (size_t)blockIdx.x * 256 + tid;
        size_t row = i >> 10;
        size_t c4  = i & 1023;
        const float* src = (c4 < 512) ? (x + row * 2048 + c4 * 4)
                                      : (h + row * 2048 + (c4 - 512) * 4);
        float4 v = *(const float4*)src;
        *(__half2*)(g_A + row * 4096 + c4 * 4)     = __floats2half2_rn(v.x, v.y);
        *(__half2*)(g_A + row * 4096 + c4 * 4 + 2) = __floats2half2_rn(v.z, v.w);
    } else {
        __shared__ float tile[32][33];
        int bid = blockIdx.x - 16384;
        int kt = bid & 127;
        int ct = (bid >> 7) & 63;
        int g  = bid >> 13;
        int tx = tid & 31, ty = tid >> 5;
        int k0 = kt * 32, c0 = ct * 32;
        const float* src;
        int krel = (k0 < 2048) ? k0 : k0 - 2048;
        if (k0 < 2048)
            src = (g == 0) ? wxi : (g == 1) ? wxf : (g == 2) ? wxo : wxc;
        else
            src = (g == 0) ? whi : (g == 1) ? whf : (g == 2) ? who : whc;
        #pragma unroll
        for (int r = ty; r < 32; r += 8)
            tile[r][tx] = src[(size_t)(krel + r) * 2048 + c0 + tx];
        __syncthreads();
        #pragma unroll
        for (int r = ty; r < 32; r += 8) {
            size_t n = (size_t)(c0 + r) * 4 + g;
            g_B[n * 4096 + k0 + tx] = __float2half_rn(tile[tx][r]);
        }
    }
}

// ================= main fused GEMM + LSTM =================
__global__ void __launch_bounds__(THREADS, 1) lstm_gemm_kernel(
    const float* __restrict__ c_in,
    const float* __restrict__ b_i, const float* __restrict__ b_f,
    const float* __restrict__ b_o, const float* __restrict__ b_c,
    float* __restrict__ out) {
    extern __shared__ float sm[];
    float* bias_sm = sm;                       // 128 floats [hc*4+gate]
    __half* stage  = (__half*)(sm + 128);

    const int tid  = threadIdx.x;
    const int lane = tid & 31;
    const int wid  = tid >> 5;
    const int wm   = wid >> 1;                 // 0..3 -> m offset wm*64
    const int wn   = wid & 1;                  // 0..1 -> n offset wn*64
    const int m0   = blockIdx.x * BM;
    const int n0   = blockIdx.y * BN;
    const int hc0  = blockIdx.y * 32;

    if (tid < 128) {
        int g = tid & 3, hc = tid >> 2;
        const float* bp = (g == 0) ? b_i : (g == 1) ? b_f : (g == 2) ? b_o : b_c;
        bias_sm[tid] = bp[hc0 + hc];
    }

    const uint32_t stage_u32 = (uint32_t)__cvta_generic_to_shared(stage);

    // -------- cp.async stage issue: A 2048 + B 1024 chunks (16B each) --------
    auto issue = [&](int s, int kt) {
        uint32_t As = stage_u32 + (uint32_t)(s * STAGE_H) * 2;
        uint32_t Bs = As + AHALVES * 2;
        int k0 = kt * BK;
        #pragma unroll
        for (int it = 0; it < 8; it++) {               // A
            int ch  = tid + it * THREADS;
            int row = ch >> 3, kc = ch & 7;
            cp16(As + (uint32_t)(row * APITCH + kc * 8) * 2,
                 g_A + (size_t)(m0 + row) * 4096 + k0 + kc * 8);
        }
        #pragma unroll
        for (int it = 0; it < 4; it++) {               // B
            int ch  = tid + it * THREADS;
            int row = ch >> 3, kc = ch & 7;
            cp16(Bs + (uint32_t)(row * BPITCH + kc * 8) * 2,
                 g_B + (size_t)(n0 + row) * 4096 + k0 + kc * 8);
        }
    };

    issue(0, 0); CP_COMMIT();
    issue(1, 1); CP_COMMIT();

    float acc[4][8][4];
    #pragma unroll
    for (int a = 0; a < 4; a++)
        #pragma unroll
        for (int b = 0; b < 8; b++)
            #pragma unroll
            for (int q = 0; q < 4; q++) acc[a][b][q] = 0.0f;

    // ldmatrix lane offsets
    const uint32_t a_lane_off =
        ((uint32_t)((wm * 64 + (lane & 15)) * APITCH + (lane >> 4) * 8)) * 2;
    const uint32_t b_lane_off =
        ((uint32_t)((wn * 64 + (lane & 7) + ((lane >> 4) << 3)) * BPITCH
                    + ((lane >> 3) & 1) * 8)) * 2;

    // double-buffered fragments
    uint32_t af[2][16], bf[2][16];

    auto ldsm_chunk = [&](int buf, uint32_t As, uint32_t Bs, int k16) {
        uint32_t koff = (uint32_t)k16 * 32;            // 16 halves = 32 B
        #pragma unroll
        for (int ms = 0; ms < 4; ms++)
            LDSM4(af[buf][ms * 4 + 0], af[buf][ms * 4 + 1],
                  af[buf][ms * 4 + 2], af[buf][ms * 4 + 3],
                  As + a_lane_off + (uint32_t)(ms * 16 * APITCH) * 2 + koff);
        #pragma unroll
        for (int np = 0; np < 4; np++)
            LDSM4(bf[buf][np * 4 + 0], bf[buf][np * 4 + 1],
                  bf[buf][np * 4 + 2], bf[buf][np * 4 + 3],
                  Bs + b_lane_off + (uint32_t)(np * 16 * BPITCH) * 2 + koff);
    };

    auto mma_chunk = [&](int buf) {
        #pragma unroll
        for (int ms = 0; ms < 4; ms++)
            #pragma unroll
            for (int ns = 0; ns < 8; ns++)
                MMA16(acc[ms][ns], &af[buf][ms * 4],
                      &bf[buf][(ns >> 1) * 4 + (ns & 1) * 2]);
    };

    int s = 0;
    for (int kt = 0; kt < NKT; kt++) {
        CP_WAIT(1);
        __syncthreads();
        uint32_t As = stage_u32 + (uint32_t)(s * STAGE_H) * 2;
        uint32_t Bs = As + AHALVES * 2;
        ldsm_chunk(0, As, Bs, 0);
        #pragma unroll
        for (int c = 0; c < 4; c++) {
            if (c < 3) ldsm_chunk((c + 1) & 1, As, Bs, c + 1);
            else if (kt + 2 < NKT) issue((kt + 2) % 3, kt + 2);
            mma_chunk(c & 1);
        }
        CP_COMMIT();
        s++; if (s == 3) s = 0;
    }

    CP_WAIT(0);
    __syncthreads();

    // -------- epilogue --------
    float* ebase = sm + 128;
    float* cbuf  = ebase;
    float* hbuf  = ebase + EBUF_W;
    float* cobuf = ebase + 2 * EBUF_W;

    #pragma unroll
    for (int it = 0; it < 8; it++) {
        int idx = tid + it * THREADS;                  // 2048 float4 loads
        int row = idx >> 3, q = idx & 7;
        float4 v = *(const float4*)(c_in + (size_t)(m0 + row) * 2048 + hc0 + q * 4);
        float* d = cbuf + row * EPITCH + q * 4;
        d[0] = v.x; d[1] = v.y; d[2] = v.z; d[3] = v.w;
    }
    __syncthreads();

    const bool odd = lane & 1;
    #pragma unroll
    for (int ms = 0; ms < 4; ms++) {
        #pragma unroll
        for (int ns = 0; ns < 8; ns++) {
            float t0 = __shfl_xor_sync(0xFFFFFFFFu, acc[ms][ns][0], 1);
            float t1 = __shfl_xor_sync(0xFFFFFFFFu, acc[ms][ns][1], 1);
            float t2 = __shfl_xor_sync(0xFFFFFFFFu, acc[ms][ns][2], 1);
            float t3 = __shfl_xor_sync(0xFFFFFFFFu, acc[ms][ns][3], 1);
            float gi = odd ? t2 : acc[ms][ns][0];
            float gf = odd ? t3 : acc[ms][ns][1];
            float go = odd ? acc[ms][ns][2] : t0;
            float gg = odd ? acc[ms][ns][3] : t1;
            int rowl = wm * 64 + ms * 16 + (lane >> 2) + (odd ? 8 : 0);
            int hc   = wn * 16 + ns * 2 + ((lane >> 1) & 1);
            gi += bias_sm[hc * 4 + 0];
            gf += bias_sm[hc * 4 + 1];
            go += bias_sm[hc * 4 + 2];
            gg += bias_sm[hc * 4 + 3];
            float it_ = sigm(gi);
            float ft_ = sigm(gf);
            float ot_ = sigm(go);
            float ct  = cbuf[rowl * EPITCH + hc] * ft_ + it_ * tanh_f(gg);
            float ht  = ot_ * tanh_f(ct);
            hbuf[rowl * EPITCH + hc]  = ht;
            cobuf[rowl * EPITCH + hc] = ct;
        }
    }
    __syncthreads();

    float* out_c = out + (size_t)4096 * 2048;
    #pragma unroll
    for (int it = 0; it < 8; it++) {
        int idx = tid + it * THREADS;
        int row = idx >> 3, q = idx & 7;
        size_t g = (size_t)(m0 + row) * 2048 + hc0 + q * 4;
        const float* hsrc = hbuf + row * EPITCH + q * 4;
        const float* csrc = cobuf + row * EPITCH + q * 4;
        float4 hv = {hsrc[0], hsrc[1], hsrc[2], hsrc[3]};
        float4 cv = {csrc[0], csrc[1], csrc[2], csrc[3]};
        *(float4*)(out + g)   = hv;
        *(float4*)(out_c + g) = cv;
    }
}

// ================= host =================
extern "C" void kernel_launch(void* const* d_in, const int* in_sizes, int n_in,
                              void* d_out, int out_size) {
    (void)in_sizes; (void)n_in; (void)out_size;
    const float* x    = (const float*)d_in[0];
    const float* h    = (const float*)d_in[1];
    const float* c    = (const float*)d_in[2];
    const float* w_xi = (const float*)d_in[3];
    const float* w_hi = (const float*)d_in[4];
    const float* w_xf = (const float*)d_in[5];
    const float* w_hf = (const float*)d_in[6];
    const float* w_xo = (const float*)d_in[7];
    const float* w_ho = (const float*)d_in[8];
    const float* w_xc = (const float*)d_in[9];
    const float* w_hc = (const float*)d_in[10];
    const float* b_i  = (const float*)d_in[11];
    const float* b_f  = (const float*)d_in[12];
    const float* b_o  = (const float*)d_in[13];
    const float* b_c  = (const float*)d_in[14];

    conv_kernel<<<49152, 256>>>(x, h, w_xi, w_xf, w_xo, w_xc,
                                w_hi, w_hf, w_ho, w_hc);

    cudaFuncSetAttribute(lstm_gemm_kernel,
                         cudaFuncAttributeMaxDynamicSharedMemorySize, SMEM_BYTES);
    dim3 grid(Mdim / BM, Ndim / BN, 1);   // (16, 64)
    lstm_gemm_kernel<<<grid, THREADS, SMEM_BYTES>>>(c, b_i, b_f, b_o, b_c, (float*)d_out);
}